// round 6
// baseline (speedup 1.0000x reference)
#include <cuda_runtime.h>
#include <cstdint>
#include <cstddef>

#define T_STEPS 2048
#define BATCH   512
#define HID     33
#define ODIM    18
#define H1DIM   72
#define NE      2            // batch elements per CTA
#define NTH     (66 * NE)    // 132 threads

// Per-layer outputs y[t][b][k] (t-major). Static device scratch (no allocs).
__device__ float g_y0[(size_t)T_STEPS * BATCH * HID];
__device__ float g_y1[(size_t)T_STEPS * BATCH * HID];

typedef unsigned long long u64;

__device__ __forceinline__ void fma2(u64 &acc, u64 a, u64 b) {
    asm("fma.rn.f32x2 %0, %1, %2, %0;" : "+l"(acc) : "l"(a), "l"(b));
}
__device__ __forceinline__ u64 pack2(float lo, float hi) {
    u64 r; asm("mov.b64 %0, {%1,%2};" : "=l"(r) : "f"(lo), "f"(hi)); return r;
}
__device__ __forceinline__ float2 unpack2(u64 v) {
    float2 r; asm("mov.b64 {%0,%1}, %2;" : "=f"(r.x), "=f"(r.y) : "l"(v)); return r;
}
__device__ __forceinline__ float sigm_(float x) {
    return __fdividef(1.f, 1.f + __expf(-x));
}
__device__ __forceinline__ float tanh_(float x) {
    float e = __expf(2.f * x);
    return 1.f - __fdividef(2.f, e + 1.f);
}

// One CTA = NE batch elements. Per element, 66 threads: s = 2r + half.
//   half 0: gates (i_r, g_r)      half 1: gates (f_r, o_r)
// Pair threads (s even / s odd) are always adjacent lanes of one warp
// (all pair-start tids even), so the cell update needs only one shuffle.
// One __syncthreads per step; h/x double-buffered in shared.
//
// IN:   input width (11 for layer 0, 33 otherwise)
// XBF:  x layout [B,T,IN] (layer 0) vs [T,B,HID] (y buffers)
// XSRC: -1 = xin param, 0 = g_y0, 1 = g_y1
// YDST: -1 = no per-step output, 0 = g_y0, 1 = g_y1
template<int IN, bool XBF, int XSRC, int YDST>
__global__ __launch_bounds__(NTH, 2)
void lstm_layer_kernel(const float* __restrict__ xin,
                       const float* __restrict__ Wih,
                       const float* __restrict__ Whh,
                       const float* __restrict__ bih,
                       const float* __restrict__ bhh,
                       float* __restrict__ hid)
{
    constexpr int XV  = (IN <= 12) ? 3 : 9;   // ulonglong2 vectors for x
    constexpr int NPX = 2 * XV;               // packed weight pairs for x
    const int tid  = threadIdx.x;
    const int e    = tid / 66;
    const int s    = tid % 66;
    const int r    = s >> 1;
    const int half = s & 1;
    const int b    = blockIdx.x * NE + e;

    const int rowA = half ? (HID + r)     : r;            // f : i
    const int rowB = half ? (3 * HID + r) : (2 * HID + r); // o : g

    __shared__ __align__(16) float h_sh[NE][2][36];
    __shared__ __align__(16) float x_sh[NE][2][36];

    const float* xp = (XSRC == 0) ? g_y0 : (XSRC == 1) ? g_y1 : xin;
    float* yp = (YDST == 0) ? g_y0 : (YDST == 1) ? g_y1 : nullptr;

    // ---- pack weights into f32x2 registers (once) ----
    u64 wa_h[18], wb_h[18];
#pragma unroll
    for (int p = 0; p < 18; p++) {
        int m = 2 * p;
        float a0 = (m     < HID) ? Whh[rowA * HID + m]     : 0.f;
        float a1 = (m + 1 < HID) ? Whh[rowA * HID + m + 1] : 0.f;
        float b0 = (m     < HID) ? Whh[rowB * HID + m]     : 0.f;
        float b1 = (m + 1 < HID) ? Whh[rowB * HID + m + 1] : 0.f;
        wa_h[p] = pack2(a0, a1);
        wb_h[p] = pack2(b0, b1);
    }
    u64 wa_x[NPX], wb_x[NPX];
#pragma unroll
    for (int p = 0; p < NPX; p++) {
        int m = 2 * p;
        float a0 = (m     < IN) ? Wih[rowA * IN + m]     : 0.f;
        float a1 = (m + 1 < IN) ? Wih[rowA * IN + m + 1] : 0.f;
        float b0 = (m     < IN) ? Wih[rowB * IN + m]     : 0.f;
        float b1 = (m + 1 < IN) ? Wih[rowB * IN + m + 1] : 0.f;
        wa_x[p] = pack2(a0, a1);
        wb_x[p] = pack2(b0, b1);
    }
    const float biasA = bih[rowA] + bhh[rowA];
    const float biasB = bih[rowB] + bhh[rowB];

    // shuffle mask for (possibly partial) last warp
    const int lanebase = tid & ~31;
    const int nlanes   = (NTH - lanebase >= 32) ? 32 : (NTH - lanebase);
    const unsigned mask = (nlanes == 32) ? 0xFFFFFFFFu : ((1u << nlanes) - 1u);

    const bool ldr = (half == 0) && (r < IN);   // x loaders

    auto xval = [&](int t, int i) -> float {
        if (XBF) return xp[((size_t)b * T_STEPS + t) * IN + i];
        else     return xp[((size_t)t * BATCH + b) * HID + i];
    };

    // ---- init shared state (both parities zero) ----
    for (int i = tid; i < NE * 2 * 36; i += NTH) (&h_sh[0][0][0])[i] = 0.f;
    for (int i = tid; i < NE * 2 * 36; i += NTH) (&x_sh[0][0][0])[i] = 0.f;
    __syncthreads();
    if (ldr) x_sh[e][0][r] = xval(0, r);
    __syncthreads();

    float c  = 0.f;
    float xr = ldr ? xval(1, r) : 0.f;   // x(t+1) entering step t

    for (int t = 0; t < T_STEPS; ++t) {
        const int pc = t & 1;       // current parity
        const int pn = pc ^ 1;      // next parity

        // depth-2 x prefetch (long-scoreboard hidden across steps)
        float xr2 = 0.f;
        if (ldr && (t + 2) < T_STEPS) xr2 = xval(t + 2, r);

        // 4 independent f32x2 accumulation chains
        u64 aAh = 0ull, aBh = 0ull, aAx = 0ull, aBx = 0ull;
        const ulonglong2* hv = (const ulonglong2*)h_sh[e][pc];
        const ulonglong2* xv = (const ulonglong2*)x_sh[e][pc];
#pragma unroll
        for (int q = 0; q < 9; q++) {
            ulonglong2 v = hv[q];                  // one LDS.128, broadcast
            fma2(aAh, wa_h[2 * q],     v.x);
            fma2(aBh, wb_h[2 * q],     v.x);
            fma2(aAh, wa_h[2 * q + 1], v.y);
            fma2(aBh, wb_h[2 * q + 1], v.y);
        }
#pragma unroll
        for (int q = 0; q < XV; q++) {
            ulonglong2 v = xv[q];
            fma2(aAx, wa_x[2 * q],     v.x);
            fma2(aBx, wb_x[2 * q],     v.x);
            fma2(aAx, wa_x[2 * q + 1], v.y);
            fma2(aBx, wb_x[2 * q + 1], v.y);
        }
        float2 vAh = unpack2(aAh), vAx = unpack2(aAx);
        float2 vBh = unpack2(aBh), vBx = unpack2(aBx);
        float preA = (vAh.x + vAh.y) + (vAx.x + vAx.y) + biasA;
        float preB = (vBh.x + vBh.y) + (vBx.x + vBx.y) + biasB;

        float aA = sigm_(preA);                       // i or f
        float aB = half ? sigm_(preB) : tanh_(preB);  // o or g
        float p  = aA * aB;                           // half0: sigm(i)*tanh(g)
        float ig = __shfl_xor_sync(mask, p, 1);       // to partner lane

        if (half) {
            c = aA * c + ig;                 // f*c + i*g
            float hn = aB * tanh_(c);        // o*tanh(c)
            h_sh[e][pn][r] = hn;
            if (YDST >= 0) yp[((size_t)t * BATCH + b) * HID + r] = hn;
            if (t == T_STEPS - 1) hid[b * HID + r] = hn;
        } else if (ldr) {
            x_sh[e][pn][r] = xr;             // publish x(t+1)
            xr = xr2;
        }
        __syncthreads();   // h_t and x_{t+1} visible; all reads of pc done
    }
}

// MLP head: out = GELU(hid@W1^T + b1) @ W2^T + b2, one block per row.
__global__ __launch_bounds__(H1DIM)
void head_kernel(const float* __restrict__ hid,
                 const float* __restrict__ W1, const float* __restrict__ b1,
                 const float* __restrict__ W2, const float* __restrict__ b2,
                 float* __restrict__ out)
{
    const int rr = blockIdx.x;
    const int u  = threadIdx.x;
    __shared__ float hrow[HID];
    __shared__ float h1[H1DIM];

    if (u < HID) hrow[u] = hid[rr * HID + u];
    __syncthreads();

    float s = b1[u];
#pragma unroll
    for (int m = 0; m < HID; m++) s += W1[u * HID + m] * hrow[m];
    h1[u] = 0.5f * s * (1.f + erff(s * 0.70710678118654752f));  // exact GELU
    __syncthreads();

    if (u < ODIM) {
        float s2 = b2[u];
#pragma unroll
        for (int m = 0; m < H1DIM; m++) s2 += W2[u * H1DIM + m] * h1[m];
        out[rr * ODIM + u] = s2;
    }
}

extern "C" void kernel_launch(void* const* d_in, const int* in_sizes, int n_in,
                              void* d_out, int out_size)
{
    const float* x    = (const float*)d_in[0];
    const float* Wih0 = (const float*)d_in[1];
    const float* Whh0 = (const float*)d_in[2];
    const float* bih0 = (const float*)d_in[3];
    const float* bhh0 = (const float*)d_in[4];
    const float* Wih1 = (const float*)d_in[5];
    const float* Whh1 = (const float*)d_in[6];
    const float* bih1 = (const float*)d_in[7];
    const float* bhh1 = (const float*)d_in[8];
    const float* Wih2 = (const float*)d_in[9];
    const float* Whh2 = (const float*)d_in[10];
    const float* bih2 = (const float*)d_in[11];
    const float* bhh2 = (const float*)d_in[12];
    const float* W1   = (const float*)d_in[13];
    const float* b1   = (const float*)d_in[14];
    const float* W2   = (const float*)d_in[15];
    const float* b2   = (const float*)d_in[16];

    float* out = (float*)d_out;                      // [3, 512, 18]
    float* hid = out + 3 * BATCH * ODIM;             // [3, 512, 33]

    const int grid = BATCH / NE;   // 256

    lstm_layer_kernel<11, true,  -1, 0><<<grid, NTH>>>(
        x, Wih0, Whh0, bih0, bhh0, hid);
    lstm_layer_kernel<33, false,  0, 1><<<grid, NTH>>>(
        nullptr, Wih1, Whh1, bih1, bhh1, hid + BATCH * HID);
    lstm_layer_kernel<33, false,  1, -1><<<grid, NTH>>>(
        nullptr, Wih2, Whh2, bih2, bhh2, hid + 2 * BATCH * HID);
    head_kernel<<<3 * BATCH, H1DIM>>>(hid, W1, b1, W2, b2, out);
}

// round 7
// speedup vs baseline: 1.0051x; 1.0051x over previous
#include <cuda_runtime.h>
#include <cstdint>
#include <cstddef>

#define T_STEPS 2048
#define BATCH   512
#define HID     33
#define G4      132
#define ODIM    18
#define H1DIM   72
#define XSTRIDE (BATCH * G4)   // per-t stride in xg

// Static device scratch (allocation-free per harness rules).
// xg: [T][B][132] gate preactivations (bias absorbed), reused across layers.
// y:  [T][B][33]  layer output, reused (y0 consumed by xg1 before y1 overwrites).
__device__ float g_xg[(size_t)T_STEPS * BATCH * G4];
__device__ float g_y [(size_t)T_STEPS * BATCH * HID];

typedef unsigned long long u64;

__device__ __forceinline__ void fma2(u64 &acc, u64 a, u64 b) {
    asm("fma.rn.f32x2 %0, %1, %2, %0;" : "+l"(acc) : "l"(a), "l"(b));
}
__device__ __forceinline__ u64 pack2(float lo, float hi) {
    u64 r; asm("mov.b64 %0, {%1,%2};" : "=l"(r) : "f"(lo), "f"(hi)); return r;
}
__device__ __forceinline__ float2 unpack2(u64 v) {
    float2 r; asm("mov.b64 {%0,%1}, %2;" : "=f"(r.x), "=f"(r.y) : "l"(v)); return r;
}
__device__ __forceinline__ float sigm_(float x) {
    return __fdividef(1.f, 1.f + __expf(-x));
}
__device__ __forceinline__ float tanh_(float x) {
    float e = __expf(2.f * x);
    return 1.f - __fdividef(2.f, e + 1.f);
}

// ---------------------------------------------------------------------------
// xg precompute: xg[t][b][j] = Wih[j]·x_t(b) + b_ih[j] + b_hh[j]
// One block = one t, 16 consecutive b. 132 threads, thread j owns gate row j
// (weights register-resident, f32x2-packed). 528B-coalesced output stores.
// XBF: layer0 input x [B,T,11]; else g_y [T,B,33].
// ---------------------------------------------------------------------------
template<int IN, bool XBF>
__global__ __launch_bounds__(G4)
void xg_kernel(const float* __restrict__ xin,
               const float* __restrict__ Wih,
               const float* __restrict__ bih,
               const float* __restrict__ bhh)
{
    constexpr int NP = (IN + 1) / 2 + (((IN + 1) / 2) & 1);  // 6 (IN=11) / 18 (IN=33)
    constexpr int INP = 2 * NP;                               // 12 / 36 padded
    const int t  = blockIdx.y;
    const int b0 = blockIdx.x * 16;
    const int j  = threadIdx.x;

    __shared__ __align__(16) float x_sh[16][INP];

    // zero-pad, then cooperative load of 16 input rows
    for (int i = j; i < 16 * INP; i += G4) (&x_sh[0][0])[i] = 0.f;
    __syncthreads();
    if (XBF) {
        for (int i = j; i < 16 * IN; i += G4) {
            int row = i / IN, col = i % IN;
            x_sh[row][col] = xin[((size_t)(b0 + row) * T_STEPS + t) * IN + col];
        }
    } else {
        const float* src = g_y + ((size_t)t * BATCH + b0) * HID;
        for (int i = j; i < 16 * HID; i += G4)
            x_sh[i / HID][i % HID] = src[i];   // fully coalesced
    }
    __syncthreads();

    u64 w2[NP];
#pragma unroll
    for (int p = 0; p < NP; p++) {
        int m = 2 * p;
        float lo = (m     < IN) ? Wih[j * IN + m]     : 0.f;
        float hi = (m + 1 < IN) ? Wih[j * IN + m + 1] : 0.f;
        w2[p] = pack2(lo, hi);
    }
    const float bias = bih[j] + bhh[j];

    float* outp = g_xg + ((size_t)t * BATCH + b0) * G4 + j;
#pragma unroll 4
    for (int g = 0; g < 16; g++) {
        u64 a0 = 0ull, a1 = 0ull;
        const ulonglong2* xv = (const ulonglong2*)x_sh[g];
#pragma unroll
        for (int q = 0; q < NP / 2; q++) {
            ulonglong2 v = xv[q];
            fma2(a0, w2[2 * q],     v.x);
            fma2(a1, w2[2 * q + 1], v.y);
        }
        float2 u0 = unpack2(a0), u1 = unpack2(a1);
        outp[(size_t)g * G4] = (u0.x + u0.y) + (u1.x + u1.y) + bias;
    }
}

// ---------------------------------------------------------------------------
// Recurrence: one CTA = one batch element, 132 threads (gate j per thread).
// Per step: gate = xg_reg + Whh[j]·h  (two 9-deep f32x2 chains, h from shared).
// xg streamed via depth-4 LDG register ring. h double-buffered.
// YDST: 1 = write y (layers 0,1), 0 = skip (layer 2).
// ---------------------------------------------------------------------------
template<int YDST>
__global__ __launch_bounds__(G4)
void rec_kernel(const float* __restrict__ Whh,
                float* __restrict__ hid)
{
    const int b = blockIdx.x;
    const int j = threadIdx.x;

    __shared__ __align__(16) float h_sh[2][36];
    __shared__ float g_sh[G4];

    u64 whh2[18];
#pragma unroll
    for (int p = 0; p < 18; p++) {
        int m = 2 * p;
        float lo = (m     < HID) ? Whh[j * HID + m]     : 0.f;
        float hi = (m + 1 < HID) ? Whh[j * HID + m + 1] : 0.f;
        whh2[p] = pack2(lo, hi);
    }
    const bool is_g = (j >= 66 && j < 99);   // gate order i,f,g,o

    if (j < 36) { h_sh[0][j] = 0.f; h_sh[1][j] = 0.f; }
    __syncthreads();

    const float* xgp = g_xg + (size_t)b * G4 + j;
    float x0 = xgp[0 * (size_t)XSTRIDE];
    float x1 = xgp[1 * (size_t)XSTRIDE];
    float x2 = xgp[2 * (size_t)XSTRIDE];
    float x3 = xgp[3 * (size_t)XSTRIDE];

    float c = 0.f;

    for (int t = 0; t < T_STEPS; ++t) {
        const int pc = t & 1, pn = pc ^ 1;

        float xg_t = x0;
        x0 = x1; x1 = x2; x2 = x3;
        if (t + 4 < T_STEPS) x3 = __ldg(xgp + (size_t)(t + 4) * XSTRIDE);

        u64 a0 = 0ull, a1 = 0ull;
        const ulonglong2* hv = (const ulonglong2*)h_sh[pc];
#pragma unroll
        for (int q = 0; q < 9; q++) {
            ulonglong2 v = hv[q];            // LDS.128 broadcast
            fma2(a0, whh2[2 * q],     v.x);
            fma2(a1, whh2[2 * q + 1], v.y);
        }
        float2 u0 = unpack2(a0), u1 = unpack2(a1);
        float pre = (u0.x + u0.y) + (u1.x + u1.y) + xg_t;
        g_sh[j] = is_g ? tanh_(pre) : sigm_(pre);
        __syncthreads();                     // gates visible; h_sh[pc] reads done

        if (j < HID) {
            float gi = g_sh[j];
            float gf = g_sh[j + 33];
            float gg = g_sh[j + 66];
            float go = g_sh[j + 99];
            c = gf * c + gi * gg;
            float h = go * tanh_(c);
            h_sh[pn][j] = h;
            if (YDST) g_y[((size_t)t * BATCH + b) * HID + j] = h;
            if (t == T_STEPS - 1) hid[b * HID + j] = h;
        }
        __syncthreads();                     // h_{t} visible
    }
}

// ---------------------------------------------------------------------------
// MLP head: out = GELU(hid@W1^T + b1) @ W2^T + b2
// ---------------------------------------------------------------------------
__global__ __launch_bounds__(H1DIM)
void head_kernel(const float* __restrict__ hid,
                 const float* __restrict__ W1, const float* __restrict__ b1,
                 const float* __restrict__ W2, const float* __restrict__ b2,
                 float* __restrict__ out)
{
    const int rr = blockIdx.x;
    const int u  = threadIdx.x;
    __shared__ float hrow[HID];
    __shared__ float h1[H1DIM];

    if (u < HID) hrow[u] = hid[rr * HID + u];
    __syncthreads();

    float s = b1[u];
#pragma unroll
    for (int m = 0; m < HID; m++) s += W1[u * HID + m] * hrow[m];
    h1[u] = 0.5f * s * (1.f + erff(s * 0.70710678118654752f));  // exact GELU
    __syncthreads();

    if (u < ODIM) {
        float s2 = b2[u];
#pragma unroll
        for (int m = 0; m < H1DIM; m++) s2 += W2[u * H1DIM + m] * h1[m];
        out[rr * ODIM + u] = s2;
    }
}

extern "C" void kernel_launch(void* const* d_in, const int* in_sizes, int n_in,
                              void* d_out, int out_size)
{
    const float* x    = (const float*)d_in[0];
    const float* Wih0 = (const float*)d_in[1];
    const float* Whh0 = (const float*)d_in[2];
    const float* bih0 = (const float*)d_in[3];
    const float* bhh0 = (const float*)d_in[4];
    const float* Wih1 = (const float*)d_in[5];
    const float* Whh1 = (const float*)d_in[6];
    const float* bih1 = (const float*)d_in[7];
    const float* bhh1 = (const float*)d_in[8];
    const float* Wih2 = (const float*)d_in[9];
    const float* Whh2 = (const float*)d_in[10];
    const float* bih2 = (const float*)d_in[11];
    const float* bhh2 = (const float*)d_in[12];
    const float* W1   = (const float*)d_in[13];
    const float* b1   = (const float*)d_in[14];
    const float* W2   = (const float*)d_in[15];
    const float* b2   = (const float*)d_in[16];

    float* out = (float*)d_out;                      // [3, 512, 18]
    float* hid = out + 3 * BATCH * ODIM;             // [3, 512, 33]

    dim3 ggrid(BATCH / 16, T_STEPS);                 // 32 x 2048 blocks

    // layer 0
    xg_kernel<11, true ><<<ggrid, G4>>>(x, Wih0, bih0, bhh0);
    rec_kernel<1><<<BATCH, G4>>>(Whh0, hid);
    // layer 1
    xg_kernel<33, false><<<ggrid, G4>>>(nullptr, Wih1, bih1, bhh1);
    rec_kernel<1><<<BATCH, G4>>>(Whh1, hid + BATCH * HID);
    // layer 2
    xg_kernel<33, false><<<ggrid, G4>>>(nullptr, Wih2, bih2, bhh2);
    rec_kernel<0><<<BATCH, G4>>>(Whh2, hid + 2 * BATCH * HID);
    // head
    head_kernel<<<3 * BATCH, H1DIM>>>(hid, W1, b1, W2, b2, out);
}